// round 12
// baseline (speedup 1.0000x reference)
#include <cuda_runtime.h>
#include <math.h>
#include <stdint.h>

// Problem constants
#define BB 2
#define SQ 2048
#define DD 512
#define NH 8
#define HD 64
#define SCALE 0.125f   // 1/sqrt(64)
#define CBIAS 0.5f
#define LOG2E 1.4426950408889634f
#define SCALE_L2E (SCALE * LOG2E)

// Scratch (device globals; no allocation allowed)
__device__ uint32_t g_xh[BB * SQ * (DD / 2)];    // x split bf16 hi
__device__ uint32_t g_xl[BB * SQ * (DD / 2)];    // x split bf16 lo
__device__ uint32_t g_Wqh[DD * DD / 2], g_Wql[DD * DD / 2];
__device__ uint32_t g_Wkh[DD * DD / 2], g_Wkl[DD * DD / 2];
__device__ uint32_t g_Wvh[DD * DD / 2], g_Wvl[DD * DD / 2];
__device__ uint32_t g_Woh[DD * DD / 2], g_Wol[DD * DD / 2];
__device__ uint32_t g_Qh[BB * SQ * (DD / 2)];    // Q pre-scaled split
__device__ uint32_t g_Ql[BB * SQ * (DD / 2)];
__device__ uint32_t g_Khw[BB * SQ * (DD / 2)];   // K split hi
__device__ uint32_t g_Klw[BB * SQ * (DD / 2)];   // K split lo
__device__ float    g_Vt[BB * SQ * DD];          // V tf32
__device__ uint32_t g_ctxh[BB * SQ * (DD / 2)];  // ctx split
__device__ uint32_t g_ctxl[BB * SQ * (DD / 2)];
__device__ float    g_bias[(size_t)BB * SQ * SQ]; // combined bias * log2(e)

// ---------------------------------------------------------------------------
// Precision helpers
// ---------------------------------------------------------------------------
__device__ __forceinline__ uint32_t f2tf(float f) {
    uint32_t u;
    asm("cvt.rna.tf32.f32 %0, %1;" : "=r"(u) : "f"(f));
    return u;
}
__device__ __forceinline__ uint32_t pack_bf2(float e0, float e1) {
    uint32_t r;
    asm("cvt.rn.bf16x2.f32 %0, %1, %2;" : "=r"(r) : "f"(e1), "f"(e0));
    return r;
}
__device__ __forceinline__ float bf2_lo_f(uint32_t p) { return __uint_as_float(p << 16); }
__device__ __forceinline__ float bf2_hi_f(uint32_t p) { return __uint_as_float(p & 0xffff0000u); }
__device__ __forceinline__ void split_bf2(float x, float y, uint32_t& hi, uint32_t& lo) {
    hi = pack_bf2(x, y);
    lo = pack_bf2(x - bf2_lo_f(hi), y - bf2_hi_f(hi));
}

__device__ __forceinline__ void mma_bf16(float c[4],
    uint32_t a0, uint32_t a1, uint32_t a2, uint32_t a3,
    uint32_t b0, uint32_t b1)
{
    asm volatile(
        "mma.sync.aligned.m16n8k16.row.col.f32.bf16.bf16.f32 "
        "{%0,%1,%2,%3}, {%4,%5,%6,%7}, {%8,%9}, {%0,%1,%2,%3};"
        : "+f"(c[0]), "+f"(c[1]), "+f"(c[2]), "+f"(c[3])
        : "r"(a0), "r"(a1), "r"(a2), "r"(a3), "r"(b0), "r"(b1));
}
__device__ __forceinline__ void mma_tf32(float c[4],
    uint32_t a0, uint32_t a1, uint32_t a2, uint32_t a3,
    uint32_t b0, uint32_t b1)
{
    asm volatile(
        "mma.sync.aligned.m16n8k8.row.col.f32.tf32.tf32.f32 "
        "{%0,%1,%2,%3}, {%4,%5,%6,%7}, {%8,%9}, {%0,%1,%2,%3};"
        : "+f"(c[0]), "+f"(c[1]), "+f"(c[2]), "+f"(c[3])
        : "r"(a0), "r"(a1), "r"(a2), "r"(a3), "r"(b0), "r"(b1));
}

__device__ __forceinline__ void ldsm_x4(uint32_t& r0, uint32_t& r1,
                                        uint32_t& r2, uint32_t& r3, uint32_t addr)
{
    asm volatile("ldmatrix.sync.aligned.m8n8.x4.shared.b16 {%0,%1,%2,%3}, [%4];"
        : "=r"(r0), "=r"(r1), "=r"(r2), "=r"(r3) : "r"(addr));
}

__device__ __forceinline__ uint32_t smaddr(const void* p) {
    return (uint32_t)__cvta_generic_to_shared(p);
}
#define CP16(dst, src) asm volatile("cp.async.cg.shared.global [%0], [%1], 16;" :: "r"(dst), "l"(src))
#define CPCOMMIT()     asm volatile("cp.async.commit_group;")
#define CPWAIT(n)      asm volatile("cp.async.wait_group %0;" :: "n"(n))

// ---------------------------------------------------------------------------
// Prep kernel. z=0: combined bias (pre-scaled by log2 e).
//              z=1: split x and the four weight matrices to bf16 hi/lo.
// ---------------------------------------------------------------------------
#define NPX (BB * SQ * DD / 4)          // x float2 packs = 1048576
#define NPW (DD * DD / 4)               // W float2 packs = 131072 (wait: DD*DD/2 floats2)

__global__ __launch_bounds__(256) void prep_kernel(
    const float* __restrict__ x,
    const float* __restrict__ Wq, const float* __restrict__ Wk,
    const float* __restrict__ Wv, const float* __restrict__ Wo,
    const float* __restrict__ ipa, const float* __restrict__ assoc,
    const float* __restrict__ amask,
    const int* __restrict__ cid, const unsigned char* __restrict__ kpm)
{
    const int tglob = blockIdx.x * 256 + threadIdx.x;   // 0..65535
    if (blockIdx.z == 0) {
        // Bias: grid-stride float4 over BB*SQ*SQ elements
        const int npacks = (BB * SQ * SQ) / 4;          // 2097152
        for (int p = tglob; p < npacks; p += 65536) {
            int idx = p * 4;
            int k4 = idx & (SQ - 1);
            int t2 = idx >> 11;
            int q = t2 & (SQ - 1);
            int b = t2 >> 11;

            float4 vi = *(const float4*)&ipa[idx];
            float4 va = *(const float4*)&assoc[idx];
            float4 vm = *(const float4*)&amask[q * SQ + k4];
            int4 ck4 = *(const int4*)&cid[b * SQ + k4];
            uchar4 kp4 = *(const uchar4*)&kpm[b * SQ + k4];
            int cq = cid[b * SQ + q];
            bool qv = cq >= 0;

            float r0 = vi.x + va.x + vm.x;
            float r1 = vi.y + va.y + vm.y;
            float r2 = vi.z + va.z + vm.z;
            float r3 = vi.w + va.w + vm.w;
            if (qv && cq == ck4.x && q != k4)     r0 += CBIAS;
            if (qv && cq == ck4.y && q != k4 + 1) r1 += CBIAS;
            if (qv && cq == ck4.z && q != k4 + 2) r2 += CBIAS;
            if (qv && cq == ck4.w && q != k4 + 3) r3 += CBIAS;
            if (kp4.x) r0 = -1e30f;
            if (kp4.y) r1 = -1e30f;
            if (kp4.z) r2 = -1e30f;
            if (kp4.w) r3 = -1e30f;
            *(float4*)&g_bias[idx] = make_float4(r0 * LOG2E, r1 * LOG2E,
                                                 r2 * LOG2E, r3 * LOG2E);
        }
    } else {
        // Split x + 4 weights: one float2 -> hi/lo word per pack
        const int NW2 = (DD * DD) / 2;                  // float2 packs per W = 131072
        const int total = NPX / 2 * 2;                  // keep x region = BB*SQ*DD/2 packs
        const int NX2 = (BB * SQ * DD) / 2;             // 1048576 x float2 packs
        const int ntot = NX2 + 4 * NW2;
        for (int p = tglob; p < ntot; p += 65536) {
            const float* src; uint32_t* dh; uint32_t* dl; int off;
            if (p < NX2)                { src = x;  dh = g_xh;  dl = g_xl;  off = p; }
            else if (p < NX2 + NW2)     { src = Wq; dh = g_Wqh; dl = g_Wql; off = p - NX2; }
            else if (p < NX2 + 2 * NW2) { src = Wk; dh = g_Wkh; dl = g_Wkl; off = p - NX2 - NW2; }
            else if (p < NX2 + 3 * NW2) { src = Wv; dh = g_Wvh; dl = g_Wvl; off = p - NX2 - 2 * NW2; }
            else                        { src = Wo; dh = g_Woh; dl = g_Wol; off = p - NX2 - 3 * NW2; }
            float2 v = ((const float2*)src)[off];
            split_bf2(v.x, v.y, dh[off], dl[off]);
        }
        (void)total;
    }
}

// ---------------------------------------------------------------------------
// Streaming split-operand bf16x3 GEMM. Operands are pre-split bf16 hi/lo
// word arrays [rows][DD/2]. cp.async 2-stage pipeline, one barrier/iter.
// BM=128, BN=64, BK=32 (16 words). 8 warps, warp = 16r x 64c.
// MODE: 0 = fp32 C, 1 = K split words, 2 = V tf32, 3 = Q scaled split.
// ---------------------------------------------------------------------------
#define GP2 20
#define GSTG_A (128 * GP2)
#define GSTG_W (64 * GP2)
#define GSTG (2 * GSTG_A + 2 * GSTG_W)   // words per stage = 7680
#define GEMM_SMEM2 (2 * GSTG * 4)        // 61440 bytes

template <int MODE>
__device__ __forceinline__ void gemm_split_body(
    const uint32_t* __restrict__ Ah, const uint32_t* __restrict__ Al,
    const uint32_t* __restrict__ Wh, const uint32_t* __restrict__ Wl,
    const float* __restrict__ bias, float* __restrict__ C,
    int m0, int n0)
{
    extern __shared__ uint32_t smu[];

    const int tid = threadIdx.x;
    const int w = tid >> 5, lane = tid & 31;
    const int g = lane >> 2, t = lane & 3;
    const int lm_m = lane >> 3, lm_r = lane & 7;

    float acc[8][4] = {};

    // issue stage s covering word-col base k0w
    auto issue = [&](int s, int k0w) {
        uint32_t* ah = smu + s * GSTG;
        uint32_t* al = ah + GSTG_A;
        uint32_t* wh = al + GSTG_A;
        uint32_t* wl = wh + GSTG_W;
        #pragma unroll
        for (int i = 0; i < 2; i++) {
            int e = tid + i * 256;          // 0..511
            int r = e >> 2, c4 = (e & 3) * 4;
            CP16(smaddr(ah + r * GP2 + c4), Ah + (size_t)(m0 + r) * (DD / 2) + k0w + c4);
            CP16(smaddr(al + r * GP2 + c4), Al + (size_t)(m0 + r) * (DD / 2) + k0w + c4);
        }
        {
            int r = tid >> 2, c4 = (tid & 3) * 4;   // r 0..63
            CP16(smaddr(wh + r * GP2 + c4), Wh + (size_t)(n0 + r) * (DD / 2) + k0w + c4);
            CP16(smaddr(wl + r * GP2 + c4), Wl + (size_t)(n0 + r) * (DD / 2) + k0w + c4);
        }
        CPCOMMIT();
    };

    issue(0, 0);

    for (int it = 0; it < 16; it++) {
        CPWAIT(0);
        __syncthreads();
        if (it + 1 < 16) issue((it + 1) & 1, (it + 1) * 16);

        uint32_t* ah_s = smu + (it & 1) * GSTG;
        uint32_t* al_s = ah_s + GSTG_A;
        uint32_t* wh_s = al_s + GSTG_A;
        uint32_t* wl_s = wh_s + GSTG_W;

        #pragma unroll
        for (int kk = 0; kk < 2; kk++) {
            uint32_t ah0, ah1, ah2, ah3, al0, al1, al2, al3;
            {
                int arow = w * 16 + (lm_m & 1) * 8 + lm_r;
                int acol = kk * 8 + (lm_m >> 1) * 4;
                ldsm_x4(ah0, ah1, ah2, ah3, smaddr(ah_s + arow * GP2 + acol));
                ldsm_x4(al0, al1, al2, al3, smaddr(al_s + arow * GP2 + acol));
            }
            #pragma unroll
            for (int np = 0; np < 4; np++) {
                int brow = (2 * np + (lm_m >> 1)) * 8 + lm_r;
                int bcol = kk * 8 + (lm_m & 1) * 4;
                uint32_t bh0, bh1, bh2, bh3, bl0, bl1, bl2, bl3;
                ldsm_x4(bh0, bh1, bh2, bh3, smaddr(wh_s + brow * GP2 + bcol));
                ldsm_x4(bl0, bl1, bl2, bl3, smaddr(wl_s + brow * GP2 + bcol));
                mma_bf16(acc[2*np],   ah0, ah1, ah2, ah3, bh0, bh1);
                mma_bf16(acc[2*np],   ah0, ah1, ah2, ah3, bl0, bl1);
                mma_bf16(acc[2*np],   al0, al1, al2, al3, bh0, bh1);
                mma_bf16(acc[2*np+1], ah0, ah1, ah2, ah3, bh2, bh3);
                mma_bf16(acc[2*np+1], ah0, ah1, ah2, ah3, bl2, bl3);
                mma_bf16(acc[2*np+1], al0, al1, al2, al3, bh2, bh3);
            }
        }
    }

    // Epilogue
    #pragma unroll
    for (int ns = 0; ns < 8; ns++) {
        int n = n0 + ns * 8 + 2 * t;
        float b0 = bias[n], b1 = bias[n + 1];
        int r = m0 + w * 16 + g;
        float v00 = acc[ns][0] + b0, v01 = acc[ns][1] + b1;
        float v10 = acc[ns][2] + b0, v11 = acc[ns][3] + b1;
        size_t wcol = (size_t)(n >> 1);
        if (MODE == 0) {
            *(float2*)&C[(size_t)r * DD + n] = make_float2(v00, v01);
            *(float2*)&C[(size_t)(r + 8) * DD + n] = make_float2(v10, v11);
        } else if (MODE == 1) {
            uint32_t hi0, lo0, hi1, lo1;
            split_bf2(v00, v01, hi0, lo0);
            split_bf2(v10, v11, hi1, lo1);
            g_Khw[(size_t)r * (DD / 2) + wcol] = hi0;
            g_Klw[(size_t)r * (DD / 2) + wcol] = lo0;
            g_Khw[(size_t)(r + 8) * (DD / 2) + wcol] = hi1;
            g_Klw[(size_t)(r + 8) * (DD / 2) + wcol] = lo1;
        } else if (MODE == 2) {
            *(float2*)&g_Vt[(size_t)r * DD + n] =
                make_float2(__uint_as_float(f2tf(v00)), __uint_as_float(f2tf(v01)));
            *(float2*)&g_Vt[(size_t)(r + 8) * DD + n] =
                make_float2(__uint_as_float(f2tf(v10)), __uint_as_float(f2tf(v11)));
        } else {
            uint32_t hi0, lo0, hi1, lo1;
            split_bf2(v00 * SCALE_L2E, v01 * SCALE_L2E, hi0, lo0);
            split_bf2(v10 * SCALE_L2E, v11 * SCALE_L2E, hi1, lo1);
            g_Qh[(size_t)r * (DD / 2) + wcol] = hi0;
            g_Ql[(size_t)r * (DD / 2) + wcol] = lo0;
            g_Qh[(size_t)(r + 8) * (DD / 2) + wcol] = hi1;
            g_Ql[(size_t)(r + 8) * (DD / 2) + wcol] = lo1;
        }
    }
}

__global__ __launch_bounds__(256, 2) void qkv_tc_kernel(
    const float* __restrict__ bq, const float* __restrict__ bk,
    const float* __restrict__ bv)
{
    int m0 = blockIdx.y * 128, n0 = blockIdx.x * 64;
    if (blockIdx.z == 0)
        gemm_split_body<3>(g_xh, g_xl, g_Wqh, g_Wql, bq, nullptr, m0, n0);
    else if (blockIdx.z == 1)
        gemm_split_body<1>(g_xh, g_xl, g_Wkh, g_Wkl, bk, nullptr, m0, n0);
    else
        gemm_split_body<2>(g_xh, g_xl, g_Wvh, g_Wvl, bv, nullptr, m0, n0);
}

__global__ __launch_bounds__(256, 2) void proj_tc_kernel(
    const float* __restrict__ bo, float* __restrict__ out)
{
    gemm_split_body<0>(g_ctxh, g_ctxl, g_Woh, g_Wol, bo, out,
                       blockIdx.y * 128, blockIdx.x * 64);
}

// ---------------------------------------------------------------------------
// Tensor-core flash attention, cp.async 2-stage pipeline, ONE barrier/tile.
// Q fragments read pre-scaled/split directly from gmem.
// ---------------------------------------------------------------------------
#define KP 36
#define VP 72
#define PP 68
#define KSTG (64 * KP)
#define VSTG (64 * VP)
#define ATTN_SMEM ((2 * KSTG * 2 + 2 * VSTG + 128 * PP) * 4)
#define NKT (SQ / 64)

__global__ __launch_bounds__(256, 2) void attn_tc_kernel()
{
    extern __shared__ uint32_t smu[];
    uint32_t* KhiS = smu;                       // 2 stages
    uint32_t* KloS = KhiS + 2 * KSTG;
    float* VsS = (float*)(KloS + 2 * KSTG);     // 2 stages
    float* Ps  = VsS + 2 * VSTG;                // 128*PP (P staging)

    const int tid = threadIdx.x;
    const int w = tid >> 5, lane = tid & 31;
    const int g = lane >> 2, t = lane & 3;
    const int q0 = blockIdx.x * 128;
    const int h  = blockIdx.y;
    const int b  = blockIdx.z;

    const uint32_t* KHsrc = g_Khw + (size_t)b * SQ * (DD / 2) + h * (HD / 2);
    const uint32_t* KLsrc = g_Klw + (size_t)b * SQ * (DD / 2) + h * (HD / 2);
    const float*    Vsrc  = g_Vt  + (size_t)b * SQ * DD + h * HD;

    const int lm_m = lane >> 3, lm_r = lane & 7;

    // -- issue tile 0 loads immediately --
    {
        #pragma unroll
        for (int i = 0; i < 2; i++) {
            int e = tid + i * 256;
            int r = e >> 3, c4 = (e & 7) * 4;
            CP16(smaddr(KhiS + r * KP + c4), KHsrc + (size_t)r * (DD / 2) + c4);
            CP16(smaddr(KloS + r * KP + c4), KLsrc + (size_t)r * (DD / 2) + c4);
        }
        #pragma unroll
        for (int i = 0; i < 4; i++) {
            int e = tid + i * 256;
            int r = e >> 4, c4 = (e & 15) * 4;
            CP16(smaddr(VsS + r * VP + c4), Vsrc + (size_t)r * DD + c4);
        }
        CPCOMMIT();
    }

    // ---- Q fragments: direct gmem loads (pre-scaled, pre-split) ----
    const uint32_t* Qhp = g_Qh + (size_t)(b * SQ + q0) * (DD / 2) + h * (HD / 2);
    const uint32_t* Qlp = g_Ql + (size_t)(b * SQ + q0) * (DD / 2) + h * (HD / 2);
    uint32_t qh[4][4], ql[4][4];
    #pragma unroll
    for (int kk = 0; kk < 4; kk++) {
        #pragma unroll
        for (int i = 0; i < 4; i++) {
            int r = w * 16 + g + (i & 1) * 8;
            int wc = kk * 8 + t + (i >> 1) * 4;
            qh[kk][i] = Qhp[(size_t)r * (DD / 2) + wc];
            ql[kk][i] = Qlp[(size_t)r * (DD / 2) + wc];
        }
    }

    float mrow[2] = { -1e30f, -1e30f };
    float lrow[2] = { 0.0f, 0.0f };
    float o[8][4] = {};

    const float* Bg = g_bias + ((size_t)b * SQ + q0) * SQ;

    for (int kt = 0; kt < NKT; kt++) {
        CPWAIT(0);
        __syncthreads();

        if (kt + 1 < NKT) {
            int s = (kt + 1) & 1;
            int k0n = (kt + 1) * 64;
            #pragma unroll
            for (int i = 0; i < 2; i++) {
                int e = tid + i * 256;
                int r = e >> 3, c4 = (e & 7) * 4;
                CP16(smaddr(KhiS + s * KSTG + r * KP + c4),
                     KHsrc + (size_t)(k0n + r) * (DD / 2) + c4);
                CP16(smaddr(KloS + s * KSTG + r * KP + c4),
                     KLsrc + (size_t)(k0n + r) * (DD / 2) + c4);
            }
            #pragma unroll
            for (int i = 0; i < 4; i++) {
                int e = tid + i * 256;
                int r = e >> 4, c4 = (e & 15) * 4;
                CP16(smaddr(VsS + s * VSTG + r * VP + c4),
                     Vsrc + (size_t)(k0n + r) * DD + c4);
            }
            CPCOMMIT();
        }

        const uint32_t* Khi = KhiS + (kt & 1) * KSTG;
        const uint32_t* Klo = KloS + (kt & 1) * KSTG;
        const float*    Vs  = VsS  + (kt & 1) * VSTG;
        const int k0 = kt * 64;

        // ---- Bias loads early ----
        float2 bq0[8], bq1[8];
        #pragma unroll
        for (int ns = 0; ns < 8; ns++) {
            int col = k0 + ns * 8 + 2 * t;
            bq0[ns] = *(const float2*)&Bg[(size_t)(w * 16 + g) * SQ + col];
            bq1[ns] = *(const float2*)&Bg[(size_t)(w * 16 + g + 8) * SQ + col];
        }

        // ---- S = Q @ K^T (bf16x3, B-frags via ldmatrix.x4) ----
        float s[8][4] = {};
        #pragma unroll
        for (int kk = 0; kk < 4; kk++) {
            #pragma unroll
            for (int np = 0; np < 4; np++) {
                uint32_t a_hi = smaddr(Khi + ((2 * np + (lm_m >> 1)) * 8 + lm_r) * KP
                                           + kk * 8 + (lm_m & 1) * 4);
                uint32_t a_lo = smaddr(Klo + ((2 * np + (lm_m >> 1)) * 8 + lm_r) * KP
                                           + kk * 8 + (lm_m & 1) * 4);
                uint32_t bh0a, bh1a, bh0b, bh1b, bl0a, bl1a, bl0b, bl1b;
                ldsm_x4(bh0a, bh1a, bh0b, bh1b, a_hi);
                ldsm_x4(bl0a, bl1a, bl0b, bl1b, a_lo);
                mma_bf16(s[2*np],   qh[kk][0], qh[kk][1], qh[kk][2], qh[kk][3], bh0a, bh1a);
                mma_bf16(s[2*np],   qh[kk][0], qh[kk][1], qh[kk][2], qh[kk][3], bl0a, bl1a);
                mma_bf16(s[2*np],   ql[kk][0], ql[kk][1], ql[kk][2], ql[kk][3], bh0a, bh1a);
                mma_bf16(s[2*np+1], qh[kk][0], qh[kk][1], qh[kk][2], qh[kk][3], bh0b, bh1b);
                mma_bf16(s[2*np+1], qh[kk][0], qh[kk][1], qh[kk][2], qh[kk][3], bl0b, bl1b);
                mma_bf16(s[2*np+1], ql[kk][0], ql[kk][1], ql[kk][2], ql[kk][3], bh0b, bh1b);
            }
        }

        #pragma unroll
        for (int ns = 0; ns < 8; ns++) {
            s[ns][0] += bq0[ns].x; s[ns][1] += bq0[ns].y;
            s[ns][2] += bq1[ns].x; s[ns][3] += bq1[ns].y;
        }

        // ---- Online softmax (exp2, registers + quad shfl) ----
        float tm0 = -1e30f, tm1 = -1e30f;
        #pragma unroll
        for (int ns = 0; ns < 8; ns++) {
            tm0 = fmaxf(tm0, fmaxf(s[ns][0], s[ns][1]));
            tm1 = fmaxf(tm1, fmaxf(s[ns][2], s[ns][3]));
        }
        tm0 = fmaxf(tm0, __shfl_xor_sync(0xffffffffu, tm0, 1));
        tm0 = fmaxf(tm0, __shfl_xor_sync(0xffffffffu, tm0, 2));
        tm1 = fmaxf(tm1, __shfl_xor_sync(0xffffffffu, tm1, 1));
        tm1 = fmaxf(tm1, __shfl_xor_sync(0xffffffffu, tm1, 2));

        float mn0 = fmaxf(mrow[0], tm0), mn1 = fmaxf(mrow[1], tm1);
        float cr0 = exp2f(mrow[0] - mn0), cr1 = exp2f(mrow[1] - mn1);
        float sum0 = 0.0f, sum1 = 0.0f;
        const int prow = w * 16 + g;
        #pragma unroll
        for (int ns = 0; ns < 8; ns++) {
            float p0 = exp2f(s[ns][0] - mn0);
            float p1 = exp2f(s[ns][1] - mn0);
            float p2 = exp2f(s[ns][2] - mn1);
            float p3 = exp2f(s[ns][3] - mn1);
            sum0 += p0 + p1; sum1 += p2 + p3;
            int pc = ns * 8 + 2 * t;
            Ps[prow * PP + pc]           = p0;
            Ps[prow * PP + pc + 1]       = p1;
            Ps[(prow + 8) * PP + pc]     = p2;
            Ps[(prow + 8) * PP + pc + 1] = p3;
            o[ns][0] *= cr0; o[ns][1] *= cr0;
            o[ns][2] *= cr1; o[ns][3] *= cr1;
        }
        sum0 += __shfl_xor_sync(0xffffffffu, sum0, 1);
        sum0 += __shfl_xor_sync(0xffffffffu, sum0, 2);
        sum1 += __shfl_xor_sync(0xffffffffu, sum1, 1);
        sum1 += __shfl_xor_sync(0xffffffffu, sum1, 2);
        lrow[0] = lrow[0] * cr0 + sum0;
        lrow[1] = lrow[1] * cr1 + sum1;
        mrow[0] = mn0; mrow[1] = mn1;
        __syncwarp();

        // ---- O += P @ V (tf32 single-pass) ----
        #pragma unroll
        for (int kk = 0; kk < 8; kk++) {
            uint32_t a0 = __float_as_uint(Ps[prow * PP + kk * 8 + t]);
            uint32_t a1 = __float_as_uint(Ps[(prow + 8) * PP + kk * 8 + t]);
            uint32_t a2 = __float_as_uint(Ps[prow * PP + kk * 8 + t + 4]);
            uint32_t a3 = __float_as_uint(Ps[(prow + 8) * PP + kk * 8 + t + 4]);
            #pragma unroll
            for (int ns = 0; ns < 8; ns++) {
                uint32_t b0 = __float_as_uint(Vs[(kk * 8 + t) * VP + ns * 8 + g]);
                uint32_t b1 = __float_as_uint(Vs[(kk * 8 + t + 4) * VP + ns * 8 + g]);
                mma_tf32(o[ns], a0, a1, a2, a3, b0, b1);
            }
        }
    }

    // ---- Normalize + write ctx as split bf16 ----
    float inv0 = 1.0f / lrow[0], inv1 = 1.0f / lrow[1];
    uint32_t* Ch = g_ctxh + (size_t)(b * SQ + q0) * (DD / 2) + h * (HD / 2);
    uint32_t* Cl = g_ctxl + (size_t)(b * SQ + q0) * (DD / 2) + h * (HD / 2);
    #pragma unroll
    for (int ns = 0; ns < 8; ns++) {
        int wc = ns * 4 + t;
        uint32_t hi0, lo0, hi1, lo1;
        split_bf2(o[ns][0] * inv0, o[ns][1] * inv0, hi0, lo0);
        split_bf2(o[ns][2] * inv1, o[ns][3] * inv1, hi1, lo1);
        Ch[(size_t)(w * 16 + g) * (DD / 2) + wc] = hi0;
        Cl[(size_t)(w * 16 + g) * (DD / 2) + wc] = lo0;
        Ch[(size_t)(w * 16 + g + 8) * (DD / 2) + wc] = hi1;
        Cl[(size_t)(w * 16 + g + 8) * (DD / 2) + wc] = lo1;
    }
}

// ---------------------------------------------------------------------------
extern "C" void kernel_launch(void* const* d_in, const int* in_sizes, int n_in,
                              void* d_out, int out_size)
{
    const float* x     = (const float*)d_in[0];
    const float* Wq    = (const float*)d_in[1];
    const float* bq    = (const float*)d_in[2];
    const float* Wk    = (const float*)d_in[3];
    const float* bk    = (const float*)d_in[4];
    const float* Wv    = (const float*)d_in[5];
    const float* bv    = (const float*)d_in[6];
    const float* Wo    = (const float*)d_in[7];
    const float* bo    = (const float*)d_in[8];
    const float* amask = (const float*)d_in[9];
    const float* ipa   = (const float*)d_in[10];
    const float* assoc = (const float*)d_in[11];
    const int* cid            = (const int*)d_in[12];       // int32 (JAX x64 off)
    const unsigned char* kpm  = (const unsigned char*)d_in[13];
    float* out = (float*)d_out;

    cudaFuncSetAttribute(attn_tc_kernel, cudaFuncAttributeMaxDynamicSharedMemorySize, ATTN_SMEM);
    cudaFuncSetAttribute(qkv_tc_kernel,  cudaFuncAttributeMaxDynamicSharedMemorySize, GEMM_SMEM2);
    cudaFuncSetAttribute(proj_tc_kernel, cudaFuncAttributeMaxDynamicSharedMemorySize, GEMM_SMEM2);

    // Prep: combined bias + operand splitting (memory-bound)
    prep_kernel<<<dim3(256, 1, 2), 256>>>(x, Wq, Wk, Wv, Wo,
                                          ipa, assoc, amask, cid, kpm);

    // QKV projections: streaming split-operand GEMM
    qkv_tc_kernel<<<dim3(DD / 64, (BB * SQ) / 128, 3), 256, GEMM_SMEM2>>>(bq, bk, bv);

    // Tensor-core flash attention
    attn_tc_kernel<<<dim3(SQ / 128, NH, BB), 256, ATTN_SMEM>>>();

    // Output projection
    proj_tc_kernel<<<dim3(DD / 64, (BB * SQ) / 128), 256, GEMM_SMEM2>>>(bo, out);
}

// round 13
// speedup vs baseline: 1.0434x; 1.0434x over previous
#include <cuda_runtime.h>
#include <cuda_fp16.h>
#include <math.h>
#include <stdint.h>

// Problem constants
#define BB 2
#define SQ 2048
#define DD 512
#define NH 8
#define HD 64
#define SCALE 0.125f   // 1/sqrt(64)
#define CBIAS 0.5f
#define LOG2E 1.4426950408889634f
#define SCALE_L2E (SCALE * LOG2E)

// Scratch (device globals; no allocation allowed)
__device__ uint32_t g_Qh[BB * SQ * (DD / 2)];    // Q pre-scaled split bf16 hi
__device__ uint32_t g_Ql[BB * SQ * (DD / 2)];    // Q split lo
__device__ uint32_t g_Khw[BB * SQ * (DD / 2)];   // K split hi
__device__ uint32_t g_Klw[BB * SQ * (DD / 2)];   // K split lo
__device__ float    g_Vt[BB * SQ * DD];          // V tf32
__device__ uint32_t g_ctxh[BB * SQ * (DD / 2)];  // ctx split hi
__device__ uint32_t g_ctxl[BB * SQ * (DD / 2)];  // ctx split lo
__device__ uint32_t g_Woh[DD * DD / 2], g_Wol[DD * DD / 2];  // Wo split
__device__ uint32_t g_bias_h[(size_t)BB * SQ * SQ / 2]; // combined bias*log2e, half2 pairs

// ---------------------------------------------------------------------------
// Precision helpers
// ---------------------------------------------------------------------------
__device__ __forceinline__ uint32_t f2tf(float f) {
    uint32_t u;
    asm("cvt.rna.tf32.f32 %0, %1;" : "=r"(u) : "f"(f));
    return u;
}
__device__ __forceinline__ uint32_t pack_bf2(float e0, float e1) {
    uint32_t r;
    asm("cvt.rn.bf16x2.f32 %0, %1, %2;" : "=r"(r) : "f"(e1), "f"(e0));
    return r;
}
__device__ __forceinline__ float bf2_lo_f(uint32_t p) { return __uint_as_float(p << 16); }
__device__ __forceinline__ float bf2_hi_f(uint32_t p) { return __uint_as_float(p & 0xffff0000u); }
__device__ __forceinline__ void split_bf2(float x, float y, uint32_t& hi, uint32_t& lo) {
    hi = pack_bf2(x, y);
    lo = pack_bf2(x - bf2_lo_f(hi), y - bf2_hi_f(hi));
}

__device__ __forceinline__ void mma_bf16(float c[4],
    uint32_t a0, uint32_t a1, uint32_t a2, uint32_t a3,
    uint32_t b0, uint32_t b1)
{
    asm volatile(
        "mma.sync.aligned.m16n8k16.row.col.f32.bf16.bf16.f32 "
        "{%0,%1,%2,%3}, {%4,%5,%6,%7}, {%8,%9}, {%0,%1,%2,%3};"
        : "+f"(c[0]), "+f"(c[1]), "+f"(c[2]), "+f"(c[3])
        : "r"(a0), "r"(a1), "r"(a2), "r"(a3), "r"(b0), "r"(b1));
}
__device__ __forceinline__ void mma_tf32(float c[4],
    uint32_t a0, uint32_t a1, uint32_t a2, uint32_t a3,
    uint32_t b0, uint32_t b1)
{
    asm volatile(
        "mma.sync.aligned.m16n8k8.row.col.f32.tf32.tf32.f32 "
        "{%0,%1,%2,%3}, {%4,%5,%6,%7}, {%8,%9}, {%0,%1,%2,%3};"
        : "+f"(c[0]), "+f"(c[1]), "+f"(c[2]), "+f"(c[3])
        : "r"(a0), "r"(a1), "r"(a2), "r"(a3), "r"(b0), "r"(b1));
}

__device__ __forceinline__ void ldsm_x4(uint32_t& r0, uint32_t& r1,
                                        uint32_t& r2, uint32_t& r3, uint32_t addr)
{
    asm volatile("ldmatrix.sync.aligned.m8n8.x4.shared.b16 {%0,%1,%2,%3}, [%4];"
        : "=r"(r0), "=r"(r1), "=r"(r2), "=r"(r3) : "r"(addr));
}

__device__ __forceinline__ uint32_t smaddr(const void* p) {
    return (uint32_t)__cvta_generic_to_shared(p);
}
#define CP16(dst, src) asm volatile("cp.async.cg.shared.global [%0], [%1], 16;" :: "r"(dst), "l"(src))
#define CPCOMMIT()     asm volatile("cp.async.commit_group;")
#define CPWAIT(n)      asm volatile("cp.async.wait_group %0;" :: "n"(n))

// ---------------------------------------------------------------------------
// In-loop-convert bf16x3 GEMM (R11 pattern): raw fp32 A/W in, all fragment
// reads via ldmatrix.x4. BM=128, BN=64, BK=32. 8 warps, warp = 16r x 64c.
// MODE: 1 = K split, 2 = V tf32, 3 = Q pre-scaled split.
// ---------------------------------------------------------------------------
#define AP 20
#define GEMM_SMEM ((128 * AP * 2 + 64 * AP * 2) * 4)

template <int MODE>
__device__ __forceinline__ void gemm_tc_body(
    const float* __restrict__ A, const float* __restrict__ W,
    const float* __restrict__ bias, int m0, int n0)
{
    extern __shared__ uint32_t smu[];
    uint32_t* Ahi = smu;
    uint32_t* Alo = Ahi + 128 * AP;
    uint32_t* Whi = Alo + 128 * AP;
    uint32_t* Wlo = Whi + 64 * AP;

    const int tid = threadIdx.x;
    const int w = tid >> 5, lane = tid & 31;
    const int g = lane >> 2, t = lane & 3;
    const int lm_m = lane >> 3, lm_r = lane & 7;

    float acc[8][4] = {};
    float2 pa[8], pw[4];

    #pragma unroll
    for (int i = 0; i < 8; i++) {
        int e = tid + i * 256;
        int r = e >> 4, c2 = e & 15;
        pa[i] = *(const float2*)&A[(size_t)(m0 + r) * DD + 2 * c2];
    }
    #pragma unroll
    for (int i = 0; i < 4; i++) {
        int e = tid + i * 256;
        int r = e >> 4, c2 = e & 15;
        pw[i] = *(const float2*)&W[(size_t)(n0 + r) * DD + 2 * c2];
    }

    for (int k0 = 0; k0 < DD; k0 += 32) {
        #pragma unroll
        for (int i = 0; i < 8; i++) {
            int e = tid + i * 256;
            int r = e >> 4, c2 = e & 15;
            split_bf2(pa[i].x, pa[i].y, Ahi[r * AP + c2], Alo[r * AP + c2]);
        }
        #pragma unroll
        for (int i = 0; i < 4; i++) {
            int e = tid + i * 256;
            int r = e >> 4, c2 = e & 15;
            split_bf2(pw[i].x, pw[i].y, Whi[r * AP + c2], Wlo[r * AP + c2]);
        }
        __syncthreads();

        if (k0 + 32 < DD) {
            #pragma unroll
            for (int i = 0; i < 8; i++) {
                int e = tid + i * 256;
                int r = e >> 4, c2 = e & 15;
                pa[i] = *(const float2*)&A[(size_t)(m0 + r) * DD + k0 + 32 + 2 * c2];
            }
            #pragma unroll
            for (int i = 0; i < 4; i++) {
                int e = tid + i * 256;
                int r = e >> 4, c2 = e & 15;
                pw[i] = *(const float2*)&W[(size_t)(n0 + r) * DD + k0 + 32 + 2 * c2];
            }
        }

        #pragma unroll
        for (int kk = 0; kk < 2; kk++) {
            uint32_t ah0, ah1, ah2, ah3, al0, al1, al2, al3;
            {
                int arow = w * 16 + (lm_m & 1) * 8 + lm_r;
                int acol = kk * 8 + (lm_m >> 1) * 4;
                ldsm_x4(ah0, ah1, ah2, ah3, smaddr(Ahi + arow * AP + acol));
                ldsm_x4(al0, al1, al2, al3, smaddr(Alo + arow * AP + acol));
            }
            #pragma unroll
            for (int np = 0; np < 4; np++) {
                int brow = (2 * np + (lm_m >> 1)) * 8 + lm_r;
                int bcol = kk * 8 + (lm_m & 1) * 4;
                uint32_t bh0, bh1, bh2, bh3, bl0, bl1, bl2, bl3;
                ldsm_x4(bh0, bh1, bh2, bh3, smaddr(Whi + brow * AP + bcol));
                ldsm_x4(bl0, bl1, bl2, bl3, smaddr(Wlo + brow * AP + bcol));
                mma_bf16(acc[2*np],   ah0, ah1, ah2, ah3, bh0, bh1);
                mma_bf16(acc[2*np],   ah0, ah1, ah2, ah3, bl0, bl1);
                mma_bf16(acc[2*np],   al0, al1, al2, al3, bh0, bh1);
                mma_bf16(acc[2*np+1], ah0, ah1, ah2, ah3, bh2, bh3);
                mma_bf16(acc[2*np+1], ah0, ah1, ah2, ah3, bl2, bl3);
                mma_bf16(acc[2*np+1], al0, al1, al2, al3, bh2, bh3);
            }
        }
        __syncthreads();
    }

    // Epilogue
    #pragma unroll
    for (int ns = 0; ns < 8; ns++) {
        int n = n0 + ns * 8 + 2 * t;
        float b0 = bias[n], b1 = bias[n + 1];
        int r = m0 + w * 16 + g;
        float v00 = acc[ns][0] + b0, v01 = acc[ns][1] + b1;
        float v10 = acc[ns][2] + b0, v11 = acc[ns][3] + b1;
        size_t wcol = (size_t)(n >> 1);
        if (MODE == 1) {
            uint32_t hi0, lo0, hi1, lo1;
            split_bf2(v00, v01, hi0, lo0);
            split_bf2(v10, v11, hi1, lo1);
            g_Khw[(size_t)r * (DD / 2) + wcol] = hi0;
            g_Klw[(size_t)r * (DD / 2) + wcol] = lo0;
            g_Khw[(size_t)(r + 8) * (DD / 2) + wcol] = hi1;
            g_Klw[(size_t)(r + 8) * (DD / 2) + wcol] = lo1;
        } else if (MODE == 2) {
            *(float2*)&g_Vt[(size_t)r * DD + n] =
                make_float2(__uint_as_float(f2tf(v00)), __uint_as_float(f2tf(v01)));
            *(float2*)&g_Vt[(size_t)(r + 8) * DD + n] =
                make_float2(__uint_as_float(f2tf(v10)), __uint_as_float(f2tf(v11)));
        } else {
            uint32_t hi0, lo0, hi1, lo1;
            split_bf2(v00 * SCALE_L2E, v01 * SCALE_L2E, hi0, lo0);
            split_bf2(v10 * SCALE_L2E, v11 * SCALE_L2E, hi1, lo1);
            g_Qh[(size_t)r * (DD / 2) + wcol] = hi0;
            g_Ql[(size_t)r * (DD / 2) + wcol] = lo0;
            g_Qh[(size_t)(r + 8) * (DD / 2) + wcol] = hi1;
            g_Ql[(size_t)(r + 8) * (DD / 2) + wcol] = lo1;
        }
    }
}

// ---------------------------------------------------------------------------
// Fused QKV + bias/Wo-split kernel. z in {0,1,2}: GEMM planes.
// z == 3: combined fp16 bias + Wo split (memory-bound, overlaps GEMMs).
// ---------------------------------------------------------------------------
__global__ __launch_bounds__(256, 2) void qkv_bias_kernel(
    const float* __restrict__ x,
    const float* __restrict__ Wq, const float* __restrict__ bq,
    const float* __restrict__ Wk, const float* __restrict__ bk,
    const float* __restrict__ Wv, const float* __restrict__ bv,
    const float* __restrict__ Wo,
    const float* __restrict__ ipa, const float* __restrict__ assoc,
    const float* __restrict__ amask,
    const int* __restrict__ cid, const unsigned char* __restrict__ kpm)
{
    int m0 = blockIdx.y * 128, n0 = blockIdx.x * 64;
    if (blockIdx.z == 0) {
        gemm_tc_body<3>(x, Wq, bq, m0, n0);
    } else if (blockIdx.z == 1) {
        gemm_tc_body<1>(x, Wk, bk, m0, n0);
    } else if (blockIdx.z == 2) {
        gemm_tc_body<2>(x, Wv, bv, m0, n0);
    } else {
        const int nthreads = gridDim.x * gridDim.y * 256;   // 65536
        const int tglob = (blockIdx.y * gridDim.x + blockIdx.x) * 256 + threadIdx.x;
        // Bias: float4 packs -> two half2 words each
        const int npacks = (BB * SQ * SQ) / 4;              // 2097152
        for (int p = tglob; p < npacks; p += nthreads) {
            int idx = p * 4;
            int k4 = idx & (SQ - 1);
            int t2 = idx >> 11;
            int q = t2 & (SQ - 1);
            int b = t2 >> 11;

            float4 vi = *(const float4*)&ipa[idx];
            float4 va = *(const float4*)&assoc[idx];
            float4 vm = *(const float4*)&amask[q * SQ + k4];
            int4 ck4 = *(const int4*)&cid[b * SQ + k4];
            uchar4 kp4 = *(const uchar4*)&kpm[b * SQ + k4];
            int cq = cid[b * SQ + q];
            bool qv = cq >= 0;

            float r0 = (vi.x + va.x + vm.x) * LOG2E;
            float r1 = (vi.y + va.y + vm.y) * LOG2E;
            float r2 = (vi.z + va.z + vm.z) * LOG2E;
            float r3 = (vi.w + va.w + vm.w) * LOG2E;
            const float cb = CBIAS * LOG2E;
            if (qv && cq == ck4.x && q != k4)     r0 += cb;
            if (qv && cq == ck4.y && q != k4 + 1) r1 += cb;
            if (qv && cq == ck4.z && q != k4 + 2) r2 += cb;
            if (qv && cq == ck4.w && q != k4 + 3) r3 += cb;
            if (kp4.x) r0 = -60000.0f;
            if (kp4.y) r1 = -60000.0f;
            if (kp4.z) r2 = -60000.0f;
            if (kp4.w) r3 = -60000.0f;
            __half2 h01 = __floats2half2_rn(r0, r1);
            __half2 h23 = __floats2half2_rn(r2, r3);
            uint32_t w01, w23;
            memcpy(&w01, &h01, 4); memcpy(&w23, &h23, 4);
            g_bias_h[(size_t)p * 2]     = w01;
            g_bias_h[(size_t)p * 2 + 1] = w23;
        }
        // Wo split: float2 packs
        const int NW2 = (DD * DD) / 2;                      // 131072
        for (int p = tglob; p < NW2; p += nthreads) {
            float2 v = ((const float2*)Wo)[p];
            split_bf2(v.x, v.y, g_Woh[p], g_Wol[p]);
        }
    }
}

// ---------------------------------------------------------------------------
// Streaming split-operand GEMM (proj): pre-split ctx @ pre-split Wo^T.
// cp.async 2-stage pipeline, one barrier/iter.
// ---------------------------------------------------------------------------
#define GP2 20
#define GSTG_A (128 * GP2)
#define GSTG_W (64 * GP2)
#define GSTG (2 * GSTG_A + 2 * GSTG_W)
#define GEMM_SMEM2 (2 * GSTG * 4)

__global__ __launch_bounds__(256, 2) void proj_tc_kernel(
    const float* __restrict__ bo, float* __restrict__ out)
{
    extern __shared__ uint32_t smu[];
    const int m0 = blockIdx.y * 128, n0 = blockIdx.x * 64;

    const int tid = threadIdx.x;
    const int w = tid >> 5, lane = tid & 31;
    const int g = lane >> 2, t = lane & 3;
    const int lm_m = lane >> 3, lm_r = lane & 7;

    float acc[8][4] = {};

    auto issue = [&](int s, int k0w) {
        uint32_t* ah = smu + s * GSTG;
        uint32_t* al = ah + GSTG_A;
        uint32_t* wh = al + GSTG_A;
        uint32_t* wl = wh + GSTG_W;
        #pragma unroll
        for (int i = 0; i < 2; i++) {
            int e = tid + i * 256;
            int r = e >> 2, c4 = (e & 3) * 4;
            CP16(smaddr(ah + r * GP2 + c4), g_ctxh + (size_t)(m0 + r) * (DD / 2) + k0w + c4);
            CP16(smaddr(al + r * GP2 + c4), g_ctxl + (size_t)(m0 + r) * (DD / 2) + k0w + c4);
        }
        {
            int r = tid >> 2, c4 = (tid & 3) * 4;
            CP16(smaddr(wh + r * GP2 + c4), g_Woh + (size_t)(n0 + r) * (DD / 2) + k0w + c4);
            CP16(smaddr(wl + r * GP2 + c4), g_Wol + (size_t)(n0 + r) * (DD / 2) + k0w + c4);
        }
        CPCOMMIT();
    };

    issue(0, 0);

    for (int it = 0; it < 16; it++) {
        CPWAIT(0);
        __syncthreads();
        if (it + 1 < 16) issue((it + 1) & 1, (it + 1) * 16);

        uint32_t* ah_s = smu + (it & 1) * GSTG;
        uint32_t* al_s = ah_s + GSTG_A;
        uint32_t* wh_s = al_s + GSTG_A;
        uint32_t* wl_s = wh_s + GSTG_W;

        #pragma unroll
        for (int kk = 0; kk < 2; kk++) {
            uint32_t ah0, ah1, ah2, ah3, al0, al1, al2, al3;
            {
                int arow = w * 16 + (lm_m & 1) * 8 + lm_r;
                int acol = kk * 8 + (lm_m >> 1) * 4;
                ldsm_x4(ah0, ah1, ah2, ah3, smaddr(ah_s + arow * GP2 + acol));
                ldsm_x4(al0, al1, al2, al3, smaddr(al_s + arow * GP2 + acol));
            }
            #pragma unroll
            for (int np = 0; np < 4; np++) {
                int brow = (2 * np + (lm_m >> 1)) * 8 + lm_r;
                int bcol = kk * 8 + (lm_m & 1) * 4;
                uint32_t bh0, bh1, bh2, bh3, bl0, bl1, bl2, bl3;
                ldsm_x4(bh0, bh1, bh2, bh3, smaddr(wh_s + brow * GP2 + bcol));
                ldsm_x4(bl0, bl1, bl2, bl3, smaddr(wl_s + brow * GP2 + bcol));
                mma_bf16(acc[2*np],   ah0, ah1, ah2, ah3, bh0, bh1);
                mma_bf16(acc[2*np],   ah0, ah1, ah2, ah3, bl0, bl1);
                mma_bf16(acc[2*np],   al0, al1, al2, al3, bh0, bh1);
                mma_bf16(acc[2*np+1], ah0, ah1, ah2, ah3, bh2, bh3);
                mma_bf16(acc[2*np+1], ah0, ah1, ah2, ah3, bl2, bl3);
                mma_bf16(acc[2*np+1], al0, al1, al2, al3, bh2, bh3);
            }
        }
    }

    #pragma unroll
    for (int ns = 0; ns < 8; ns++) {
        int n = n0 + ns * 8 + 2 * t;
        float b0 = bo[n], b1 = bo[n + 1];
        int r = m0 + w * 16 + g;
        *(float2*)&out[(size_t)r * DD + n] = make_float2(acc[ns][0] + b0, acc[ns][1] + b1);
        *(float2*)&out[(size_t)(r + 8) * DD + n] = make_float2(acc[ns][2] + b0, acc[ns][3] + b1);
    }
}

// ---------------------------------------------------------------------------
// Tensor-core flash attention, cp.async 2-stage pipeline, ONE barrier/tile.
// Q fragments direct from gmem (pre-scaled split). fp16 combined bias.
// ---------------------------------------------------------------------------
#define KP 36
#define VP 72
#define PP 68
#define KSTG (64 * KP)
#define VSTG (64 * VP)
#define ATTN_SMEM ((2 * KSTG * 2 + 2 * VSTG + 128 * PP) * 4)
#define NKT (SQ / 64)

__global__ __launch_bounds__(256, 2) void attn_tc_kernel()
{
    extern __shared__ uint32_t smu[];
    uint32_t* KhiS = smu;
    uint32_t* KloS = KhiS + 2 * KSTG;
    float* VsS = (float*)(KloS + 2 * KSTG);
    float* Ps  = VsS + 2 * VSTG;

    const int tid = threadIdx.x;
    const int w = tid >> 5, lane = tid & 31;
    const int g = lane >> 2, t = lane & 3;
    const int q0 = blockIdx.x * 128;
    const int h  = blockIdx.y;
    const int b  = blockIdx.z;

    const uint32_t* KHsrc = g_Khw + (size_t)b * SQ * (DD / 2) + h * (HD / 2);
    const uint32_t* KLsrc = g_Klw + (size_t)b * SQ * (DD / 2) + h * (HD / 2);
    const float*    Vsrc  = g_Vt  + (size_t)b * SQ * DD + h * HD;

    const int lm_m = lane >> 3, lm_r = lane & 7;

    {
        #pragma unroll
        for (int i = 0; i < 2; i++) {
            int e = tid + i * 256;
            int r = e >> 3, c4 = (e & 7) * 4;
            CP16(smaddr(KhiS + r * KP + c4), KHsrc + (size_t)r * (DD / 2) + c4);
            CP16(smaddr(KloS + r * KP + c4), KLsrc + (size_t)r * (DD / 2) + c4);
        }
        #pragma unroll
        for (int i = 0; i < 4; i++) {
            int e = tid + i * 256;
            int r = e >> 4, c4 = (e & 15) * 4;
            CP16(smaddr(VsS + r * VP + c4), Vsrc + (size_t)r * DD + c4);
        }
        CPCOMMIT();
    }

    // ---- Q fragments: direct gmem loads (pre-scaled, pre-split) ----
    const uint32_t* Qhp = g_Qh + (size_t)(b * SQ + q0) * (DD / 2) + h * (HD / 2);
    const uint32_t* Qlp = g_Ql + (size_t)(b * SQ + q0) * (DD / 2) + h * (HD / 2);
    uint32_t qh[4][4], ql[4][4];
    #pragma unroll
    for (int kk = 0; kk < 4; kk++) {
        #pragma unroll
        for (int i = 0; i < 4; i++) {
            int r = w * 16 + g + (i & 1) * 8;
            int wc = kk * 8 + t + (i >> 1) * 4;
            qh[kk][i] = Qhp[(size_t)r * (DD / 2) + wc];
            ql[kk][i] = Qlp[(size_t)r * (DD / 2) + wc];
        }
    }

    float mrow[2] = { -1e30f, -1e30f };
    float lrow[2] = { 0.0f, 0.0f };
    float o[8][4] = {};

    const uint32_t* Bgh = g_bias_h + (size_t)(b * SQ + q0) * (SQ / 2);

    for (int kt = 0; kt < NKT; kt++) {
        CPWAIT(0);
        __syncthreads();

        if (kt + 1 < NKT) {
            int s = (kt + 1) & 1;
            int k0n = (kt + 1) * 64;
            #pragma unroll
            for (int i = 0; i < 2; i++) {
                int e = tid + i * 256;
                int r = e >> 3, c4 = (e & 7) * 4;
                CP16(smaddr(KhiS + s * KSTG + r * KP + c4),
                     KHsrc + (size_t)(k0n + r) * (DD / 2) + c4);
                CP16(smaddr(KloS + s * KSTG + r * KP + c4),
                     KLsrc + (size_t)(k0n + r) * (DD / 2) + c4);
            }
            #pragma unroll
            for (int i = 0; i < 4; i++) {
                int e = tid + i * 256;
                int r = e >> 4, c4 = (e & 15) * 4;
                CP16(smaddr(VsS + s * VSTG + r * VP + c4),
                     Vsrc + (size_t)(k0n + r) * DD + c4);
            }
            CPCOMMIT();
        }

        const uint32_t* Khi = KhiS + (kt & 1) * KSTG;
        const uint32_t* Klo = KloS + (kt & 1) * KSTG;
        const float*    Vs  = VsS  + (kt & 1) * VSTG;
        const int k0 = kt * 64;

        // ---- Bias loads (fp16 pairs), early ----
        uint32_t bw0[8], bw1[8];
        #pragma unroll
        for (int ns = 0; ns < 8; ns++) {
            int wcol = (k0 + ns * 8) / 2 + t;
            bw0[ns] = Bgh[(size_t)(w * 16 + g) * (SQ / 2) + wcol];
            bw1[ns] = Bgh[(size_t)(w * 16 + g + 8) * (SQ / 2) + wcol];
        }

        // ---- S = Q @ K^T (bf16x3, B-frags via ldmatrix.x4) ----
        float s[8][4] = {};
        #pragma unroll
        for (int kk = 0; kk < 4; kk++) {
            #pragma unroll
            for (int np = 0; np < 4; np++) {
                uint32_t a_hi = smaddr(Khi + ((2 * np + (lm_m >> 1)) * 8 + lm_r) * KP
                                           + kk * 8 + (lm_m & 1) * 4);
                uint32_t a_lo = smaddr(Klo + ((2 * np + (lm_m >> 1)) * 8 + lm_r) * KP
                                           + kk * 8 + (lm_m & 1) * 4);
                uint32_t bh0a, bh1a, bh0b, bh1b, bl0a, bl1a, bl0b, bl1b;
                ldsm_x4(bh0a, bh1a, bh0b, bh1b, a_hi);
                ldsm_x4(bl0a, bl1a, bl0b, bl1b, a_lo);
                mma_bf16(s[2*np],   qh[kk][0], qh[kk][1], qh[kk][2], qh[kk][3], bh0a, bh1a);
                mma_bf16(s[2*np],   qh[kk][0], qh[kk][1], qh[kk][2], qh[kk][3], bl0a, bl1a);
                mma_bf16(s[2*np],   ql[kk][0], ql[kk][1], ql[kk][2], ql[kk][3], bh0a, bh1a);
                mma_bf16(s[2*np+1], qh[kk][0], qh[kk][1], qh[kk][2], qh[kk][3], bh0b, bh1b);
                mma_bf16(s[2*np+1], qh[kk][0], qh[kk][1], qh[kk][2], qh[kk][3], bl0b, bl1b);
                mma_bf16(s[2*np+1], ql[kk][0], ql[kk][1], ql[kk][2], ql[kk][3], bh0b, bh1b);
            }
        }

        #pragma unroll
        for (int ns = 0; ns < 8; ns++) {
            float2 b0v = __half22float2(*(const __half2*)&bw0[ns]);
            float2 b1v = __half22float2(*(const __half2*)&bw1[ns]);
            s[ns][0] += b0v.x; s[ns][1] += b0v.y;
            s[ns][2] += b1v.x; s[ns][3] += b1v.y;
        }

        // ---- Online softmax (exp2, registers + quad shfl) ----
        float tm0 = -1e30f, tm1 = -1e30f;
        #pragma unroll
        for (int ns = 0; ns < 8; ns++) {
            tm0 = fmaxf(tm0, fmaxf(s[ns][0], s[ns][1]));
            tm1 = fmaxf(tm1, fmaxf(s[ns][2], s[ns][3]));
        }
        tm0 = fmaxf(tm0, __shfl_xor_sync(0xffffffffu, tm0, 1));
        tm0 = fmaxf(tm0, __shfl_xor_sync(0xffffffffu, tm0, 2));
        tm1 = fmaxf(tm1, __shfl_xor_sync(0xffffffffu, tm1, 1));
        tm1 = fmaxf(tm1, __shfl_xor_sync(0xffffffffu, tm1, 2));

        float mn0 = fmaxf(mrow[0], tm0), mn1 = fmaxf(mrow[1], tm1);
        float cr0 = exp2f(mrow[0] - mn0), cr1 = exp2f(mrow[1] - mn1);
        float sum0 = 0.0f, sum1 = 0.0f;
        const int prow = w * 16 + g;
        #pragma unroll
        for (int ns = 0; ns < 8; ns++) {
            float p0 = exp2f(s[ns][0] - mn0);
            float p1 = exp2f(s[ns][1] - mn0);
            float p2 = exp2f(s[ns][2] - mn1);
            float p3 = exp2f(s[ns][3] - mn1);
            sum0 += p0 + p1; sum1 += p2 + p3;
            int pc = ns * 8 + 2 * t;
            Ps[prow * PP + pc]           = p0;
            Ps[prow * PP + pc + 1]       = p1;
            Ps[(prow + 8) * PP + pc]     = p2;
            Ps[(prow + 8) * PP + pc + 1] = p3;
            o[ns][0] *= cr0; o[ns][1] *= cr0;
            o[ns][2] *= cr1; o[ns][3] *= cr1;
        }
        sum0 += __shfl_xor_sync(0xffffffffu, sum0, 1);
        sum0 += __shfl_xor_sync(0xffffffffu, sum0, 2);
        sum1 += __shfl_xor_sync(0xffffffffu, sum1, 1);
        sum1 += __shfl_xor_sync(0xffffffffu, sum1, 2);
        lrow[0] = lrow[0] * cr0 + sum0;
        lrow[1] = lrow[1] * cr1 + sum1;
        mrow[0] = mn0; mrow[1] = mn1;
        __syncwarp();

        // ---- O += P @ V (tf32 single-pass) ----
        #pragma unroll
        for (int kk = 0; kk < 8; kk++) {
            uint32_t a0 = __float_as_uint(Ps[prow * PP + kk * 8 + t]);
            uint32_t a1 = __float_as_uint(Ps[(prow + 8) * PP + kk * 8 + t]);
            uint32_t a2 = __float_as_uint(Ps[prow * PP + kk * 8 + t + 4]);
            uint32_t a3 = __float_as_uint(Ps[(prow + 8) * PP + kk * 8 + t + 4]);
            #pragma unroll
            for (int ns = 0; ns < 8; ns++) {
                uint32_t b0 = __float_as_uint(Vs[(kk * 8 + t) * VP + ns * 8 + g]);
                uint32_t b1 = __float_as_uint(Vs[(kk * 8 + t + 4) * VP + ns * 8 + g]);
                mma_tf32(o[ns], a0, a1, a2, a3, b0, b1);
            }
        }
    }

    // ---- Normalize + write ctx as split bf16 ----
    float inv0 = 1.0f / lrow[0], inv1 = 1.0f / lrow[1];
    uint32_t* Ch = g_ctxh + (size_t)(b * SQ + q0) * (DD / 2) + h * (HD / 2);
    uint32_t* Cl = g_ctxl + (size_t)(b * SQ + q0) * (DD / 2) + h * (HD / 2);
    #pragma unroll
    for (int ns = 0; ns < 8; ns++) {
        int wc = ns * 4 + t;
        uint32_t hi0, lo0, hi1, lo1;
        split_bf2(o[ns][0] * inv0, o[ns][1] * inv0, hi0, lo0);
        split_bf2(o[ns][2] * inv1, o[ns][3] * inv1, hi1, lo1);
        Ch[(size_t)(w * 16 + g) * (DD / 2) + wc] = hi0;
        Cl[(size_t)(w * 16 + g) * (DD / 2) + wc] = lo0;
        Ch[(size_t)(w * 16 + g + 8) * (DD / 2) + wc] = hi1;
        Cl[(size_t)(w * 16 + g + 8) * (DD / 2) + wc] = lo1;
    }
}

// ---------------------------------------------------------------------------
extern "C" void kernel_launch(void* const* d_in, const int* in_sizes, int n_in,
                              void* d_out, int out_size)
{
    const float* x     = (const float*)d_in[0];
    const float* Wq    = (const float*)d_in[1];
    const float* bq    = (const float*)d_in[2];
    const float* Wk    = (const float*)d_in[3];
    const float* bk    = (const float*)d_in[4];
    const float* Wv    = (const float*)d_in[5];
    const float* bv    = (const float*)d_in[6];
    const float* Wo    = (const float*)d_in[7];
    const float* bo    = (const float*)d_in[8];
    const float* amask = (const float*)d_in[9];
    const float* ipa   = (const float*)d_in[10];
    const float* assoc = (const float*)d_in[11];
    const int* cid            = (const int*)d_in[12];       // int32 (JAX x64 off)
    const unsigned char* kpm  = (const unsigned char*)d_in[13];
    float* out = (float*)d_out;

    cudaFuncSetAttribute(attn_tc_kernel, cudaFuncAttributeMaxDynamicSharedMemorySize, ATTN_SMEM);
    cudaFuncSetAttribute(proj_tc_kernel, cudaFuncAttributeMaxDynamicSharedMemorySize, GEMM_SMEM2);

    // Fused QKV projections + fp16 bias + Wo split (z = 3 plane, overlapped)
    qkv_bias_kernel<<<dim3(DD / 64, (BB * SQ) / 128, 4), 256, GEMM_SMEM>>>(
        x, Wq, bq, Wk, bk, Wv, bv, Wo, ipa, assoc, amask, cid, kpm);

    // Tensor-core flash attention (2 CTAs/SM, cp.async pipelined)
    attn_tc_kernel<<<dim3(SQ / 128, NH, BB), 256, ATTN_SMEM>>>();

    // Output projection (streaming split-operand GEMM)
    proj_tc_kernel<<<dim3(DD / 64, (BB * SQ) / 128), 256, GEMM_SMEM2>>>(bo, out);
}

// round 16
// speedup vs baseline: 1.3762x; 1.3190x over previous
#include <cuda_runtime.h>
#include <cuda_fp16.h>
#include <math.h>
#include <stdint.h>

#define BB 2
#define SQ 2048
#define DD 512
#define NH 8
#define HD 64
#define SCALE 0.125f
#define CBIAS 0.5f
#define LOG2E 1.4426950408889634f
#define SCALE_L2E (SCALE * LOG2E)
#define NKT (SQ / 64)

// Scratch (device globals)
__device__ uint32_t g_Qf[BB * SQ * (DD / 2)];    // Q pre-scaled fp16x2
__device__ uint32_t g_Kf[BB * SQ * (DD / 2)];    // K fp16x2
__device__ uint32_t g_Vf[BB * SQ * (DD / 2)];    // V fp16x2 [seq][d]
__device__ uint32_t g_ctxh[BB * SQ * (DD / 2)];  // ctx split bf16 hi
__device__ uint32_t g_ctxl[BB * SQ * (DD / 2)];  // ctx split bf16 lo
__device__ uint32_t g_Woh[DD * DD / 2], g_Wol[DD * DD / 2];
__device__ uint32_t g_bias_h[(size_t)BB * SQ * SQ / 2]; // bias*log2e fp16x2

// ---- helpers ----
__device__ __forceinline__ uint32_t pack_bf2(float e0, float e1) {
    uint32_t r; asm("cvt.rn.bf16x2.f32 %0, %1, %2;" : "=r"(r) : "f"(e1), "f"(e0)); return r;
}
__device__ __forceinline__ float bf2_lo_f(uint32_t p) { return __uint_as_float(p << 16); }
__device__ __forceinline__ float bf2_hi_f(uint32_t p) { return __uint_as_float(p & 0xffff0000u); }
__device__ __forceinline__ void split_bf2(float x, float y, uint32_t& hi, uint32_t& lo) {
    hi = pack_bf2(x, y);
    lo = pack_bf2(x - bf2_lo_f(hi), y - bf2_hi_f(hi));
}
__device__ __forceinline__ uint32_t pack_h2(float a, float b) {
    __half2 h = __floats2half2_rn(a, b);
    uint32_t u; memcpy(&u, &h, 4); return u;
}
__device__ __forceinline__ uint32_t ex2_h2(uint32_t x) {
    uint32_t r; asm("ex2.approx.f16x2 %0, %1;" : "=r"(r) : "r"(x)); return r;
}
__device__ __forceinline__ float2 h2f2(uint32_t x) {
    __half2 h; memcpy(&h, &x, 4); return __half22float2(h);
}
__device__ __forceinline__ void mma_bf16(float c[4],
    uint32_t a0, uint32_t a1, uint32_t a2, uint32_t a3, uint32_t b0, uint32_t b1)
{
    asm volatile("mma.sync.aligned.m16n8k16.row.col.f32.bf16.bf16.f32 "
        "{%0,%1,%2,%3}, {%4,%5,%6,%7}, {%8,%9}, {%0,%1,%2,%3};"
        : "+f"(c[0]), "+f"(c[1]), "+f"(c[2]), "+f"(c[3])
        : "r"(a0), "r"(a1), "r"(a2), "r"(a3), "r"(b0), "r"(b1));
}
__device__ __forceinline__ void mma_f16(float c[4],
    uint32_t a0, uint32_t a1, uint32_t a2, uint32_t a3, uint32_t b0, uint32_t b1)
{
    asm volatile("mma.sync.aligned.m16n8k16.row.col.f32.f16.f16.f32 "
        "{%0,%1,%2,%3}, {%4,%5,%6,%7}, {%8,%9}, {%0,%1,%2,%3};"
        : "+f"(c[0]), "+f"(c[1]), "+f"(c[2]), "+f"(c[3])
        : "r"(a0), "r"(a1), "r"(a2), "r"(a3), "r"(b0), "r"(b1));
}
__device__ __forceinline__ void ldsm_x4(uint32_t& r0, uint32_t& r1,
                                        uint32_t& r2, uint32_t& r3, uint32_t addr)
{
    asm volatile("ldmatrix.sync.aligned.m8n8.x4.shared.b16 {%0,%1,%2,%3}, [%4];"
        : "=r"(r0), "=r"(r1), "=r"(r2), "=r"(r3) : "r"(addr));
}
__device__ __forceinline__ void ldsm_x4t(uint32_t& r0, uint32_t& r1,
                                         uint32_t& r2, uint32_t& r3, uint32_t addr)
{
    asm volatile("ldmatrix.sync.aligned.m8n8.x4.trans.shared.b16 {%0,%1,%2,%3}, [%4];"
        : "=r"(r0), "=r"(r1), "=r"(r2), "=r"(r3) : "r"(addr));
}
__device__ __forceinline__ uint32_t smaddr(const void* p) {
    return (uint32_t)__cvta_generic_to_shared(p);
}
#define CP16(dst, src) asm volatile("cp.async.cg.shared.global [%0], [%1], 16;" :: "r"(dst), "l"(src))
#define CPCOMMIT()     asm volatile("cp.async.commit_group;")
#define CPWAIT(n)      asm volatile("cp.async.wait_group %0;" :: "n"(n))

// ---------------------------------------------------------------------------
// bf16x3 GEMM: MODE 1 = K fp16, 2 = V fp16, 3 = Q scaled fp16
// ---------------------------------------------------------------------------
#define AP 20
#define GEMM_SMEM ((128 * AP * 2 + 64 * AP * 2) * 4)

template <int MODE>
__device__ __forceinline__ void gemm_tc_body(
    const float* __restrict__ A, const float* __restrict__ W,
    const float* __restrict__ bias, int m0, int n0)
{
    extern __shared__ uint32_t smu[];
    uint32_t* Ahi = smu;
    uint32_t* Alo = Ahi + 128 * AP;
    uint32_t* Whi = Alo + 128 * AP;
    uint32_t* Wlo = Whi + 64 * AP;

    const int tid = threadIdx.x;
    const int w = tid >> 5, lane = tid & 31;
    const int g = lane >> 2, t = lane & 3;
    const int lm_m = lane >> 3, lm_r = lane & 7;

    float acc[8][4] = {};
    float2 pa[8], pw[4];

    #pragma unroll
    for (int i = 0; i < 8; i++) {
        int e = tid + i * 256; int r = e >> 4, c2 = e & 15;
        pa[i] = *(const float2*)&A[(size_t)(m0 + r) * DD + 2 * c2];
    }
    #pragma unroll
    for (int i = 0; i < 4; i++) {
        int e = tid + i * 256; int r = e >> 4, c2 = e & 15;
        pw[i] = *(const float2*)&W[(size_t)(n0 + r) * DD + 2 * c2];
    }

    for (int k0 = 0; k0 < DD; k0 += 32) {
        #pragma unroll
        for (int i = 0; i < 8; i++) {
            int e = tid + i * 256; int r = e >> 4, c2 = e & 15;
            split_bf2(pa[i].x, pa[i].y, Ahi[r * AP + c2], Alo[r * AP + c2]);
        }
        #pragma unroll
        for (int i = 0; i < 4; i++) {
            int e = tid + i * 256; int r = e >> 4, c2 = e & 15;
            split_bf2(pw[i].x, pw[i].y, Whi[r * AP + c2], Wlo[r * AP + c2]);
        }
        __syncthreads();
        if (k0 + 32 < DD) {
            #pragma unroll
            for (int i = 0; i < 8; i++) {
                int e = tid + i * 256; int r = e >> 4, c2 = e & 15;
                pa[i] = *(const float2*)&A[(size_t)(m0 + r) * DD + k0 + 32 + 2 * c2];
            }
            #pragma unroll
            for (int i = 0; i < 4; i++) {
                int e = tid + i * 256; int r = e >> 4, c2 = e & 15;
                pw[i] = *(const float2*)&W[(size_t)(n0 + r) * DD + k0 + 32 + 2 * c2];
            }
        }
        #pragma unroll
        for (int kk = 0; kk < 2; kk++) {
            uint32_t ah0, ah1, ah2, ah3, al0, al1, al2, al3;
            {
                int ar = w * 16 + (lm_m & 1) * 8 + lm_r;
                int ac = kk * 8 + (lm_m >> 1) * 4;
                ldsm_x4(ah0, ah1, ah2, ah3, smaddr(Ahi + ar * AP + ac));
                ldsm_x4(al0, al1, al2, al3, smaddr(Alo + ar * AP + ac));
            }
            #pragma unroll
            for (int np = 0; np < 4; np++) {
                int br = (2 * np + (lm_m >> 1)) * 8 + lm_r;
                int bc = kk * 8 + (lm_m & 1) * 4;
                uint32_t bh0, bh1, bh2, bh3, bl0, bl1, bl2, bl3;
                ldsm_x4(bh0, bh1, bh2, bh3, smaddr(Whi + br * AP + bc));
                ldsm_x4(bl0, bl1, bl2, bl3, smaddr(Wlo + br * AP + bc));
                mma_bf16(acc[2*np],   ah0, ah1, ah2, ah3, bh0, bh1);
                mma_bf16(acc[2*np],   ah0, ah1, ah2, ah3, bl0, bl1);
                mma_bf16(acc[2*np],   al0, al1, al2, al3, bh0, bh1);
                mma_bf16(acc[2*np+1], ah0, ah1, ah2, ah3, bh2, bh3);
                mma_bf16(acc[2*np+1], ah0, ah1, ah2, ah3, bl2, bl3);
                mma_bf16(acc[2*np+1], al0, al1, al2, al3, bh2, bh3);
            }
        }
        __syncthreads();
    }

    #pragma unroll
    for (int ns = 0; ns < 8; ns++) {
        int n = n0 + ns * 8 + 2 * t;
        float b0 = bias[n], b1 = bias[n + 1];
        int r = m0 + w * 16 + g;
        float v00 = acc[ns][0] + b0, v01 = acc[ns][1] + b1;
        float v10 = acc[ns][2] + b0, v11 = acc[ns][3] + b1;
        size_t wcol = (size_t)(n >> 1);
        if (MODE == 1) {
            g_Kf[(size_t)r * (DD/2) + wcol]     = pack_h2(v00, v01);
            g_Kf[(size_t)(r+8) * (DD/2) + wcol] = pack_h2(v10, v11);
        } else if (MODE == 2) {
            g_Vf[(size_t)r * (DD/2) + wcol]     = pack_h2(v00, v01);
            g_Vf[(size_t)(r+8) * (DD/2) + wcol] = pack_h2(v10, v11);
        } else {
            g_Qf[(size_t)r * (DD/2) + wcol]     = pack_h2(v00 * SCALE_L2E, v01 * SCALE_L2E);
            g_Qf[(size_t)(r+8) * (DD/2) + wcol] = pack_h2(v10 * SCALE_L2E, v11 * SCALE_L2E);
        }
    }
}

__global__ __launch_bounds__(256, 2) void qkv_bias_kernel(
    const float* __restrict__ x,
    const float* __restrict__ Wq, const float* __restrict__ bq,
    const float* __restrict__ Wk, const float* __restrict__ bk,
    const float* __restrict__ Wv, const float* __restrict__ bv,
    const float* __restrict__ Wo,
    const float* __restrict__ ipa, const float* __restrict__ assoc,
    const float* __restrict__ amask,
    const int* __restrict__ cid, const unsigned char* __restrict__ kpm)
{
    int m0 = blockIdx.y * 128, n0 = blockIdx.x * 64;
    if (blockIdx.z == 0) gemm_tc_body<3>(x, Wq, bq, m0, n0);
    else if (blockIdx.z == 1) gemm_tc_body<1>(x, Wk, bk, m0, n0);
    else if (blockIdx.z == 2) gemm_tc_body<2>(x, Wv, bv, m0, n0);
    else {
        const int nthreads = gridDim.x * gridDim.y * 256;
        const int tglob = (blockIdx.y * gridDim.x + blockIdx.x) * 256 + threadIdx.x;
        const int npacks = (BB * SQ * SQ) / 4;
        for (int p = tglob; p < npacks; p += nthreads) {
            int idx = p * 4;
            int k4 = idx & (SQ - 1);
            int t2 = idx >> 11;
            int q = t2 & (SQ - 1);
            int b = t2 >> 11;
            float4 vi = *(const float4*)&ipa[idx];
            float4 va = *(const float4*)&assoc[idx];
            float4 vm = *(const float4*)&amask[q * SQ + k4];
            int4 ck4 = *(const int4*)&cid[b * SQ + k4];
            uchar4 kp4 = *(const uchar4*)&kpm[b * SQ + k4];
            int cq = cid[b * SQ + q];
            bool qv = cq >= 0;
            float r0 = (vi.x + va.x + vm.x) * LOG2E;
            float r1 = (vi.y + va.y + vm.y) * LOG2E;
            float r2 = (vi.z + va.z + vm.z) * LOG2E;
            float r3 = (vi.w + va.w + vm.w) * LOG2E;
            const float cb = CBIAS * LOG2E;
            if (qv && cq == ck4.x && q != k4)     r0 += cb;
            if (qv && cq == ck4.y && q != k4 + 1) r1 += cb;
            if (qv && cq == ck4.z && q != k4 + 2) r2 += cb;
            if (qv && cq == ck4.w && q != k4 + 3) r3 += cb;
            if (kp4.x) r0 = -60000.0f;
            if (kp4.y) r1 = -60000.0f;
            if (kp4.z) r2 = -60000.0f;
            if (kp4.w) r3 = -60000.0f;
            g_bias_h[(size_t)p * 2]     = pack_h2(r0, r1);
            g_bias_h[(size_t)p * 2 + 1] = pack_h2(r2, r3);
        }
        const int NW2 = (DD * DD) / 2;
        for (int p = tglob; p < NW2; p += nthreads) {
            float2 v = ((const float2*)Wo)[p];
            split_bf2(v.x, v.y, g_Woh[p], g_Wol[p]);
        }
    }
}

// ---------------------------------------------------------------------------
// Streaming proj GEMM (unchanged)
// ---------------------------------------------------------------------------
#define GP2 20
#define GSTG_A (128 * GP2)
#define GSTG_W (64 * GP2)
#define GSTG (2 * GSTG_A + 2 * GSTG_W)
#define GEMM_SMEM2 (2 * GSTG * 4)

__global__ __launch_bounds__(256, 2) void proj_tc_kernel(
    const float* __restrict__ bo, float* __restrict__ out)
{
    extern __shared__ uint32_t smu[];
    const int m0 = blockIdx.y * 128, n0 = blockIdx.x * 64;
    const int tid = threadIdx.x;
    const int w = tid >> 5, lane = tid & 31;
    const int g = lane >> 2, t = lane & 3;
    const int lm_m = lane >> 3, lm_r = lane & 7;
    float acc[8][4] = {};

    auto issue = [&](int s, int k0w) {
        uint32_t* ah = smu + s * GSTG;
        uint32_t* al = ah + GSTG_A;
        uint32_t* wh = al + GSTG_A;
        uint32_t* wl = wh + GSTG_W;
        #pragma unroll
        for (int i = 0; i < 2; i++) {
            int e = tid + i * 256; int r = e >> 2, c4 = (e & 3) * 4;
            CP16(smaddr(ah + r * GP2 + c4), g_ctxh + (size_t)(m0 + r) * (DD/2) + k0w + c4);
            CP16(smaddr(al + r * GP2 + c4), g_ctxl + (size_t)(m0 + r) * (DD/2) + k0w + c4);
        }
        {
            int r = tid >> 2, c4 = (tid & 3) * 4;
            CP16(smaddr(wh + r * GP2 + c4), g_Woh + (size_t)(n0 + r) * (DD/2) + k0w + c4);
            CP16(smaddr(wl + r * GP2 + c4), g_Wol + (size_t)(n0 + r) * (DD/2) + k0w + c4);
        }
        CPCOMMIT();
    };

    issue(0, 0);
    for (int it = 0; it < 16; it++) {
        CPWAIT(0);
        __syncthreads();
        if (it + 1 < 16) issue((it + 1) & 1, (it + 1) * 16);
        uint32_t* ah_s = smu + (it & 1) * GSTG;
        uint32_t* al_s = ah_s + GSTG_A;
        uint32_t* wh_s = al_s + GSTG_A;
        uint32_t* wl_s = wh_s + GSTG_W;
        #pragma unroll
        for (int kk = 0; kk < 2; kk++) {
            uint32_t ah0, ah1, ah2, ah3, al0, al1, al2, al3;
            {
                int ar = w * 16 + (lm_m & 1) * 8 + lm_r;
                int ac = kk * 8 + (lm_m >> 1) * 4;
                ldsm_x4(ah0, ah1, ah2, ah3, smaddr(ah_s + ar * GP2 + ac));
                ldsm_x4(al0, al1, al2, al3, smaddr(al_s + ar * GP2 + ac));
            }
            #pragma unroll
            for (int np = 0; np < 4; np++) {
                int br = (2 * np + (lm_m >> 1)) * 8 + lm_r;
                int bc = kk * 8 + (lm_m & 1) * 4;
                uint32_t bh0, bh1, bh2, bh3, bl0, bl1, bl2, bl3;
                ldsm_x4(bh0, bh1, bh2, bh3, smaddr(wh_s + br * GP2 + bc));
                ldsm_x4(bl0, bl1, bl2, bl3, smaddr(wl_s + br * GP2 + bc));
                mma_bf16(acc[2*np],   ah0, ah1, ah2, ah3, bh0, bh1);
                mma_bf16(acc[2*np],   ah0, ah1, ah2, ah3, bl0, bl1);
                mma_bf16(acc[2*np],   al0, al1, al2, al3, bh0, bh1);
                mma_bf16(acc[2*np+1], ah0, ah1, ah2, ah3, bh2, bh3);
                mma_bf16(acc[2*np+1], ah0, ah1, ah2, ah3, bl2, bl3);
                mma_bf16(acc[2*np+1], al0, al1, al2, al3, bh2, bh3);
            }
        }
    }
    #pragma unroll
    for (int ns = 0; ns < 8; ns++) {
        int n = n0 + ns * 8 + 2 * t;
        float b0 = bo[n], b1 = bo[n + 1];
        int r = m0 + w * 16 + g;
        *(float2*)&out[(size_t)r * DD + n] = make_float2(acc[ns][0] + b0, acc[ns][1] + b1);
        *(float2*)&out[(size_t)(r + 8) * DD + n] = make_float2(acc[ns][2] + b0, acc[ns][3] + b1);
    }
}

// ---------------------------------------------------------------------------
// fp16 flash attention: QK fp16 single-pass, PV fp16 single-pass, ex2.f16x2.
// cp.async 2-stage K/V pipeline, one barrier/tile, 8 warps x 16 q-rows.
// ---------------------------------------------------------------------------
#define KP3 36
#define KST (64 * KP3)            // words per K stage
#define VST (64 * KP3)            // words per V stage
#define PST (128 * KP3)
#define ATTN_SMEM ((2 * KST + 2 * VST + PST) * 4)   // 55296 B

__global__ __launch_bounds__(256, 2) void attn_tc_kernel()
{
    extern __shared__ uint32_t smu[];
    uint32_t* Kst = smu;              // 2 stages
    uint32_t* Vst = Kst + 2 * KST;    // 2 stages
    uint32_t* Pst = Vst + 2 * VST;

    const int tid = threadIdx.x;
    const int w = tid >> 5, lane = tid & 31;
    const int g = lane >> 2, t = lane & 3;
    const int lm_m = lane >> 3, lm_r = lane & 7;
    const int q0 = blockIdx.x * 128;
    const int h  = blockIdx.y;
    const int b  = blockIdx.z;

    const uint32_t* Ksrc = g_Kf + (size_t)b * SQ * (DD/2) + h * (HD/2);
    const uint32_t* Vsrc = g_Vf + (size_t)b * SQ * (DD/2) + h * (HD/2);

    // issue tile 0
    #pragma unroll
    for (int i = 0; i < 2; i++) {
        int e = tid + i * 256;        // 0..511
        int r = e >> 3, c4 = (e & 7) * 4;
        CP16(smaddr(Kst + r * KP3 + c4), Ksrc + (size_t)r * (DD/2) + c4);
        CP16(smaddr(Vst + r * KP3 + c4), Vsrc + (size_t)r * (DD/2) + c4);
    }
    CPCOMMIT();

    // Q fragments direct from gmem (pre-scaled fp16)
    const uint32_t* Qp = g_Qf + (size_t)(b * SQ + q0) * (DD/2) + h * (HD/2);
    uint32_t qf[4][4];
    #pragma unroll
    for (int kk = 0; kk < 4; kk++) {
        #pragma unroll
        for (int i = 0; i < 4; i++) {
            int r = w * 16 + g + (i & 1) * 8;
            int wc = kk * 8 + t + (i >> 1) * 4;
            qf[kk][i] = Qp[(size_t)r * (DD/2) + wc];
        }
    }

    float mrow[2] = { -1e30f, -1e30f };
    float lrow[2] = { 0.0f, 0.0f };
    float o[8][4] = {};

    const uint32_t* Bgh = g_bias_h + (size_t)(b * SQ + q0) * (SQ / 2);

    for (int kt = 0; kt < NKT; kt++) {
        CPWAIT(0);
        __syncthreads();

        if (kt + 1 < NKT) {
            int s = (kt + 1) & 1;
            int k0n = (kt + 1) * 64;
            #pragma unroll
            for (int i = 0; i < 2; i++) {
                int e = tid + i * 256;
                int r = e >> 3, c4 = (e & 7) * 4;
                CP16(smaddr(Kst + s * KST + r * KP3 + c4),
                     Ksrc + (size_t)(k0n + r) * (DD/2) + c4);
                CP16(smaddr(Vst + s * VST + r * KP3 + c4),
                     Vsrc + (size_t)(k0n + r) * (DD/2) + c4);
            }
            CPCOMMIT();
        }

        const uint32_t* Ks = Kst + (kt & 1) * KST;
        const uint32_t* Vs = Vst + (kt & 1) * VST;
        const int k0 = kt * 64;

        // bias loads early
        uint32_t bw0[8], bw1[8];
        #pragma unroll
        for (int ns = 0; ns < 8; ns++) {
            int wcol = (k0 + ns * 8) / 2 + t;
            bw0[ns] = Bgh[(size_t)(w * 16 + g) * (SQ / 2) + wcol];
            bw1[ns] = Bgh[(size_t)(w * 16 + g + 8) * (SQ / 2) + wcol];
        }

        // ---- S = Q @ K^T (fp16 single-pass) ----
        float s[8][4] = {};
        #pragma unroll
        for (int kk = 0; kk < 4; kk++) {
            #pragma unroll
            for (int np = 0; np < 4; np++) {
                int br = (2 * np + (lm_m >> 1)) * 8 + lm_r;
                int bc = kk * 8 + (lm_m & 1) * 4;
                uint32_t b0a, b1a, b0b, b1b;
                ldsm_x4(b0a, b1a, b0b, b1b, smaddr(Ks + br * KP3 + bc));
                mma_f16(s[2*np],   qf[kk][0], qf[kk][1], qf[kk][2], qf[kk][3], b0a, b1a);
                mma_f16(s[2*np+1], qf[kk][0], qf[kk][1], qf[kk][2], qf[kk][3], b0b, b1b);
            }
        }

        #pragma unroll
        for (int ns = 0; ns < 8; ns++) {
            float2 b0v = h2f2(bw0[ns]);
            float2 b1v = h2f2(bw1[ns]);
            s[ns][0] += b0v.x; s[ns][1] += b0v.y;
            s[ns][2] += b1v.x; s[ns][3] += b1v.y;
        }

        // ---- online softmax (ex2.f16x2, P stored fp16) ----
        float tm0 = -1e30f, tm1 = -1e30f;
        #pragma unroll
        for (int ns = 0; ns < 8; ns++) {
            tm0 = fmaxf(tm0, fmaxf(s[ns][0], s[ns][1]));
            tm1 = fmaxf(tm1, fmaxf(s[ns][2], s[ns][3]));
        }
        tm0 = fmaxf(tm0, __shfl_xor_sync(0xffffffffu, tm0, 1));
        tm0 = fmaxf(tm0, __shfl_xor_sync(0xffffffffu, tm0, 2));
        tm1 = fmaxf(tm1, __shfl_xor_sync(0xffffffffu, tm1, 1));
        tm1 = fmaxf(tm1, __shfl_xor_sync(0xffffffffu, tm1, 2));

        float mn0 = fmaxf(mrow[0], tm0), mn1 = fmaxf(mrow[1], tm1);
        float cr0 = exp2f(mrow[0] - mn0), cr1 = exp2f(mrow[1] - mn1);
        float sum0 = 0.0f, sum1 = 0.0f;
        const int prow = w * 16 + g;
        #pragma unroll
        for (int ns = 0; ns < 8; ns++) {
            uint32_t pa = ex2_h2(pack_h2(s[ns][0] - mn0, s[ns][1] - mn0));
            uint32_t pb = ex2_h2(pack_h2(s[ns][2] - mn1, s[ns][3] - mn1));
            Pst[prow * KP3 + ns * 4 + t]       = pa;
            Pst[(prow + 8) * KP3 + ns * 4 + t] = pb;
            float2 ua = h2f2(pa), ub = h2f2(pb);
            sum0 += ua.x + ua.y;
            sum1 += ub.x + ub.y;
            o[ns][0] *= cr0; o[ns][1] *= cr0;
            o[ns][2] *= cr1; o[ns][3] *= cr1;
        }
        sum0 += __shfl_xor_sync(0xffffffffu, sum0, 1);
        sum0 += __shfl_xor_sync(0xffffffffu, sum0, 2);
        sum1 += __shfl_xor_sync(0xffffffffu, sum1, 1);
        sum1 += __shfl_xor_sync(0xffffffffu, sum1, 2);
        lrow[0] = lrow[0] * cr0 + sum0;
        lrow[1] = lrow[1] * cr1 + sum1;
        mrow[0] = mn0; mrow[1] = mn1;
        __syncwarp();   // P rows warp-private

        // ---- O += P @ V (fp16; V via ldmatrix.trans) ----
        #pragma unroll
        for (int kk = 0; kk < 4; kk++) {
            uint32_t a0, a1, a2, a3;
            {
                int ar = w * 16 + (lm_m & 1) * 8 + lm_r;
                int ac = kk * 8 + (lm_m >> 1) * 4;
                ldsm_x4(a0, a1, a2, a3, smaddr(Pst + ar * KP3 + ac));
            }
            #pragma unroll
            for (int np = 0; np < 4; np++) {
                int krow = kk * 16 + (lane & 15);
                int colw = np * 8 + ((lane >> 4) & 1) * 4;
                uint32_t v0, v1, v2, v3;
                ldsm_x4t(v0, v1, v2, v3, smaddr(Vs + krow * KP3 + colw));
                mma_f16(o[2*np],   a0, a1, a2, a3, v0, v1);
                mma_f16(o[2*np+1], a0, a1, a2, a3, v2, v3);
            }
        }
    }

    // ---- normalize + write ctx split bf16 ----
    float inv0 = 1.0f / lrow[0], inv1 = 1.0f / lrow[1];
    uint32_t* Ch = g_ctxh + (size_t)(b * SQ + q0) * (DD/2) + h * (HD/2);
    uint32_t* Cl = g_ctxl + (size_t)(b * SQ + q0) * (DD/2) + h * (HD/2);
    #pragma unroll
    for (int ns = 0; ns < 8; ns++) {
        int wc = ns * 4 + t;
        uint32_t hi0, lo0, hi1, lo1;
        split_bf2(o[ns][0] * inv0, o[ns][1] * inv0, hi0, lo0);
        split_bf2(o[ns][2] * inv1, o[ns][3] * inv1, hi1, lo1);
        Ch[(size_t)(w * 16 + g) * (DD/2) + wc] = hi0;
        Cl[(size_t)(w * 16 + g) * (DD/2) + wc] = lo0;
        Ch[(size_t)(w * 16 + g + 8) * (DD/2) + wc] = hi1;
        Cl[(size_t)(w * 16 + g + 8) * (DD/2) + wc] = lo1;
    }
}

// ---------------------------------------------------------------------------
extern "C" void kernel_launch(void* const* d_in, const int* in_sizes, int n_in,
                              void* d_out, int out_size)
{
    const float* x     = (const float*)d_in[0];
    const float* Wq    = (const float*)d_in[1];
    const float* bq    = (const float*)d_in[2];
    const float* Wk    = (const float*)d_in[3];
    const float* bk    = (const float*)d_in[4];
    const float* Wv    = (const float*)d_in[5];
    const float* bv    = (const float*)d_in[6];
    const float* Wo    = (const float*)d_in[7];
    const float* bo    = (const float*)d_in[8];
    const float* amask = (const float*)d_in[9];
    const float* ipa   = (const float*)d_in[10];
    const float* assoc = (const float*)d_in[11];
    const int* cid            = (const int*)d_in[12];
    const unsigned char* kpm  = (const unsigned char*)d_in[13];
    float* out = (float*)d_out;

    cudaFuncSetAttribute(attn_tc_kernel, cudaFuncAttributeMaxDynamicSharedMemorySize, ATTN_SMEM);
    cudaFuncSetAttribute(proj_tc_kernel, cudaFuncAttributeMaxDynamicSharedMemorySize, GEMM_SMEM2);

    qkv_bias_kernel<<<dim3(DD / 64, (BB * SQ) / 128, 4), 256, GEMM_SMEM>>>(
        x, Wq, bq, Wk, bk, Wv, bv, Wo, ipa, assoc, amask, cid, kpm);

    attn_tc_kernel<<<dim3(SQ / 128, NH, BB), 256, ATTN_SMEM>>>();

    proj_tc_kernel<<<dim3(DD / 64, (BB * SQ) / 128), 256, GEMM_SMEM2>>>(bo, out);
}